// round 3
// baseline (speedup 1.0000x reference)
#include <cuda_runtime.h>
#include <math_constants.h>

// Problem constants
#define F        512
#define MROWS    16384          // B * QL = 16 * 1024
#define SEQ      1024
#define NHEAD    8
#define HDIM     64

// ---------------- scratch (device globals: no allocations allowed) ----------
__device__ float g_q[MROWS * F];
__device__ float g_k[MROWS * F];
__device__ float g_v[MROWS * F];
__device__ float g_ctx[MROWS * F];

// ---------------- unified SGEMM: C = [A0 | A1] @ W + bias (opt tanh) --------
// A0/A1 row stride = K0. For plain GEMM pass A1=A0, K=K0.
#define BM 128
#define BN 128
#define BK 16

__global__ __launch_bounds__(256, 2) void sgemm_bias_kernel(
    const float* __restrict__ A0, const float* __restrict__ A1,
    const float* __restrict__ W,  const float* __restrict__ bias,
    float* __restrict__ C, int N, int K0, int K, int do_tanh)
{
    __shared__ float As[BK][BM];   // A tile, transposed (k-major)
    __shared__ float Ws[BK][BN];

    const int tid = threadIdx.x;
    const int tx = tid & 15, ty = tid >> 4;
    const int bx = blockIdx.x, by = blockIdx.y;
    const int row0 = by * BM;
    const int col0 = bx * BN;

    float acc[8][8];
#pragma unroll
    for (int i = 0; i < 8; i++)
#pragma unroll
        for (int j = 0; j < 8; j++) acc[i][j] = 0.f;

    for (int kt = 0; kt < K; kt += BK) {
        const float* src = (kt < K0) ? A0 : A1;
        const int kbase = (kt < K0) ? kt : kt - K0;
        // load A tile: 128x16 floats = 512 float4, 2 per thread
#pragma unroll
        for (int i = 0; i < 2; i++) {
            int idx = tid + i * 256;         // 0..511
            int r  = idx >> 2;               // tile row 0..127
            int cv = (idx & 3) * 4;          // k offset {0,4,8,12}
            float4 v = *reinterpret_cast<const float4*>(
                src + (size_t)(row0 + r) * K0 + kbase + cv);
            As[cv + 0][r] = v.x; As[cv + 1][r] = v.y;
            As[cv + 2][r] = v.z; As[cv + 3][r] = v.w;
        }
        // load W tile: 16x128 floats = 512 float4
#pragma unroll
        for (int i = 0; i < 2; i++) {
            int idx = tid + i * 256;
            int r = idx >> 5;                // 0..15
            int c = (idx & 31) * 4;          // 0..124
            *reinterpret_cast<float4*>(&Ws[r][c]) =
                *reinterpret_cast<const float4*>(W + (size_t)(kt + r) * N + col0 + c);
        }
        __syncthreads();
#pragma unroll
        for (int kk = 0; kk < BK; kk++) {
            float a[8], b[8];
            *reinterpret_cast<float4*>(a)     = *reinterpret_cast<const float4*>(&As[kk][ty * 8]);
            *reinterpret_cast<float4*>(a + 4) = *reinterpret_cast<const float4*>(&As[kk][ty * 8 + 4]);
            *reinterpret_cast<float4*>(b)     = *reinterpret_cast<const float4*>(&Ws[kk][tx * 8]);
            *reinterpret_cast<float4*>(b + 4) = *reinterpret_cast<const float4*>(&Ws[kk][tx * 8 + 4]);
#pragma unroll
            for (int i = 0; i < 8; i++)
#pragma unroll
                for (int j = 0; j < 8; j++)
                    acc[i][j] = fmaf(a[i], b[j], acc[i][j]);
        }
        __syncthreads();
    }
#pragma unroll
    for (int i = 0; i < 8; i++) {
        int row = row0 + ty * 8 + i;
#pragma unroll
        for (int j = 0; j < 8; j += 4) {
            int col = col0 + tx * 8 + j;
            float4 v;
            v.x = acc[i][j + 0] + bias[col + 0];
            v.y = acc[i][j + 1] + bias[col + 1];
            v.z = acc[i][j + 2] + bias[col + 2];
            v.w = acc[i][j + 3] + bias[col + 3];
            if (do_tanh) {
                v.x = tanhf(v.x); v.y = tanhf(v.y);
                v.z = tanhf(v.z); v.w = tanhf(v.w);
            }
            *reinterpret_cast<float4*>(C + (size_t)row * N + col) = v;
        }
    }
}

// ---------------- flash attention: 64-query tile per block ------------------
// smem layout (floats):
//   Qst[64][65]  (d-major, padded)     4160
//   Kst[64][65]  (d-major, padded)     4160
//   Vs [64][68]  (row-major, padded)   4352
//   Ss [64][65]  (scores/probs)        4160
//   mrow[64] lrow[64] frow[64]          192
#define ATTN_SMEM_FLOATS (64*65*3 + 64*68 + 192)
#define ATTN_SMEM_BYTES  (ATTN_SMEM_FLOATS * 4)

__global__ __launch_bounds__(256) void attn_kernel()
{
    extern __shared__ float sm[];
    float* Qst  = sm;
    float* Kst  = Qst + 64 * 65;
    float* Vs   = Kst + 64 * 65;
    float* Ss   = Vs  + 64 * 68;
    float* mrow = Ss  + 64 * 65;
    float* lrow = mrow + 64;
    float* frow = lrow + 64;

    const int tid = threadIdx.x;
    const int tx = tid & 15, ty = tid >> 4;
    const int qt = blockIdx.x, h = blockIdx.y, b = blockIdx.z;
    const int qrow0 = b * SEQ + qt * 64;
    const int colh  = h * HDIM;

    // load Q tile transposed (d-major)
    for (int idx = tid; idx < 64 * 16; idx += 256) {
        int r = idx >> 4, dv = (idx & 15) * 4;
        float4 v = *reinterpret_cast<const float4*>(
            g_q + (size_t)(qrow0 + r) * F + colh + dv);
        Qst[(dv + 0) * 65 + r] = v.x; Qst[(dv + 1) * 65 + r] = v.y;
        Qst[(dv + 2) * 65 + r] = v.z; Qst[(dv + 3) * 65 + r] = v.w;
    }
    if (tid < 64) { mrow[tid] = -CUDART_INF_F; lrow[tid] = 0.f; }

    const int i0 = ty * 4, n0 = tx * 4;
    float acc[4][4] = {};

    for (int kt = 0; kt < SEQ / 64; kt++) {
        const int krow0 = b * SEQ + kt * 64;
        __syncthreads();  // prev-iter consumers done (also orders Q load / init)
        for (int idx = tid; idx < 64 * 16; idx += 256) {
            int r = idx >> 4, dv = (idx & 15) * 4;
            float4 kv = *reinterpret_cast<const float4*>(
                g_k + (size_t)(krow0 + r) * F + colh + dv);
            Kst[(dv + 0) * 65 + r] = kv.x; Kst[(dv + 1) * 65 + r] = kv.y;
            Kst[(dv + 2) * 65 + r] = kv.z; Kst[(dv + 3) * 65 + r] = kv.w;
            float4 vv = *reinterpret_cast<const float4*>(
                g_v + (size_t)(krow0 + r) * F + colh + dv);
            *reinterpret_cast<float4*>(&Vs[r * 68 + dv]) = vv;
        }
        __syncthreads();

        // S = (Q @ K^T) * 1/sqrt(D)
        float s[4][4] = {};
#pragma unroll
        for (int d = 0; d < 64; d++) {
            float a[4], bb[4];
#pragma unroll
            for (int i = 0; i < 4; i++) a[i]  = Qst[d * 65 + i0 + i];
#pragma unroll
            for (int j = 0; j < 4; j++) bb[j] = Kst[d * 65 + n0 + j];
#pragma unroll
            for (int i = 0; i < 4; i++)
#pragma unroll
                for (int j = 0; j < 4; j++)
                    s[i][j] = fmaf(a[i], bb[j], s[i][j]);
        }
#pragma unroll
        for (int i = 0; i < 4; i++)
#pragma unroll
            for (int j = 0; j < 4; j++)
                Ss[(i0 + i) * 65 + n0 + j] = s[i][j] * 0.125f;
        __syncthreads();

        // online softmax: warp w handles rows w*8..w*8+7
        {
            const int warp = tid >> 5, lane = tid & 31;
            for (int rr = 0; rr < 8; rr++) {
                const int r = warp * 8 + rr;
                float v0 = Ss[r * 65 + lane];
                float v1 = Ss[r * 65 + lane + 32];
                float mx = fmaxf(v0, v1);
#pragma unroll
                for (int off = 16; off; off >>= 1)
                    mx = fmaxf(mx, __shfl_xor_sync(0xffffffffu, mx, off));
                const float mold = mrow[r];
                const float mnew = fmaxf(mold, mx);
                const float p0 = __expf(v0 - mnew);
                const float p1 = __expf(v1 - mnew);
                float ssum = p0 + p1;
#pragma unroll
                for (int off = 16; off; off >>= 1)
                    ssum += __shfl_xor_sync(0xffffffffu, ssum, off);
                Ss[r * 65 + lane]      = p0;
                Ss[r * 65 + lane + 32] = p1;
                if (lane == 0) {
                    const float fr = __expf(mold - mnew);
                    frow[r] = fr;
                    lrow[r] = lrow[r] * fr + ssum;
                    mrow[r] = mnew;
                }
            }
        }
        __syncthreads();

        // rescale old accumulator, then O += P @ V
        float f[4];
#pragma unroll
        for (int i = 0; i < 4; i++) f[i] = frow[i0 + i];
#pragma unroll
        for (int i = 0; i < 4; i++)
#pragma unroll
            for (int n = 0; n < 4; n++) acc[i][n] *= f[i];
#pragma unroll
        for (int j = 0; j < 64; j++) {
            float a[4], bb[4];
#pragma unroll
            for (int i = 0; i < 4; i++) a[i]  = Ss[(i0 + i) * 65 + j];
#pragma unroll
            for (int n = 0; n < 4; n++) bb[n] = Vs[j * 68 + n0 + n];
#pragma unroll
            for (int i = 0; i < 4; i++)
#pragma unroll
                for (int n = 0; n < 4; n++)
                    acc[i][n] = fmaf(a[i], bb[n], acc[i][n]);
        }
    }
    __syncthreads();

#pragma unroll
    for (int i = 0; i < 4; i++) {
        const float linv = 1.f / lrow[i0 + i];
        const int row = qrow0 + i0 + i;
        float4 v;
        v.x = acc[i][0] * linv; v.y = acc[i][1] * linv;
        v.z = acc[i][2] * linv; v.w = acc[i][3] * linv;
        *reinterpret_cast<float4*>(g_ctx + (size_t)row * F + colh + n0) = v;
    }
}

// ---------------- launch ----------------------------------------------------
extern "C" void kernel_launch(void* const* d_in, const int* in_sizes, int n_in,
                              void* d_out, int out_size)
{
    const float* Q  = (const float*)d_in[0];
    const float* K  = (const float*)d_in[1];
    const float* V  = (const float*)d_in[2];
    const float* Wq = (const float*)d_in[3];
    const float* bq = (const float*)d_in[4];
    const float* Wk = (const float*)d_in[5];
    const float* bk = (const float*)d_in[6];
    const float* Wv = (const float*)d_in[7];
    const float* bv = (const float*)d_in[8];
    const float* Wo = (const float*)d_in[9];
    const float* bo = (const float*)d_in[10];
    float* out = (float*)d_out;

    float *pq, *pk, *pv, *pc;
    cudaGetSymbolAddress((void**)&pq, g_q);
    cudaGetSymbolAddress((void**)&pk, g_k);
    cudaGetSymbolAddress((void**)&pv, g_v);
    cudaGetSymbolAddress((void**)&pc, g_ctx);

    // Opt-in to >48KB dynamic smem for the attention kernel. Immediate
    // (non-stream-ordered) API: executes on the correctness call before the
    // harness begins graph capture; idempotent on later calls.
    cudaFuncSetAttribute(attn_kernel,
                         cudaFuncAttributeMaxDynamicSharedMemorySize,
                         ATTN_SMEM_BYTES);

    const dim3 gproj(F / BN, MROWS / BM);   // (4, 128)

    // QKV projections
    sgemm_bias_kernel<<<gproj, 256>>>(Q, Q, Wq, bq, pq, F, F, F, 0);
    sgemm_bias_kernel<<<gproj, 256>>>(K, K, Wk, bk, pk, F, F, F, 0);
    sgemm_bias_kernel<<<gproj, 256>>>(V, V, Wv, bv, pv, F, F, F, 0);

    // attention
    attn_kernel<<<dim3(SEQ / 64, NHEAD, 16), 256, ATTN_SMEM_BYTES>>>();

    // output: tanh([ctx | Q] @ Wo + bo)  (concat folded via split-K)
    sgemm_bias_kernel<<<gproj, 256>>>(pc, Q, Wo, bo, out, F, F, 2 * F, 1);
}

// round 7
// speedup vs baseline: 1.2462x; 1.2462x over previous
#include <cuda_runtime.h>
#include <cuda_bf16.h>
#include <math_constants.h>
#include <cstdint>

// Problem constants
#define F        512
#define MROWS    16384          // B * QL = 16 * 1024
#define SEQ      1024
#define NHEAD    8
#define HDIM     64

// ===================== scratch (device globals) =============================
__device__ float g_q[MROWS * F];
__device__ float g_k[MROWS * F];
__device__ float g_v[MROWS * F];
__device__ float g_ctx[MROWS * F];

// bf16 hi/lo splits of GEMM A operands
__device__ __nv_bfloat16 g_qin_hi[MROWS * F], g_qin_lo[MROWS * F];
__device__ __nv_bfloat16 g_kin_hi[MROWS * F], g_kin_lo[MROWS * F];
__device__ __nv_bfloat16 g_vin_hi[MROWS * F], g_vin_lo[MROWS * F];
__device__ __nv_bfloat16 g_ctx_hi[MROWS * F], g_ctx_lo[MROWS * F];
// transposed weight splits [N, K]
__device__ __nv_bfloat16 g_wqt_hi[F * F], g_wqt_lo[F * F];
__device__ __nv_bfloat16 g_wkt_hi[F * F], g_wkt_lo[F * F];
__device__ __nv_bfloat16 g_wvt_hi[F * F], g_wvt_lo[F * F];
__device__ __nv_bfloat16 g_wot_hi[F * 2 * F], g_wot_lo[F * 2 * F];

// ===================== fp32 -> bf16 hi/lo split =============================
__global__ __launch_bounds__(256) void split_kernel(
    const float4* __restrict__ in, __nv_bfloat16* __restrict__ hi,
    __nv_bfloat16* __restrict__ lo, int n4)
{
    int i = blockIdx.x * 256 + threadIdx.x;
    if (i >= n4) return;
    float4 v = in[i];
    __nv_bfloat16 h0 = __float2bfloat16(v.x);
    __nv_bfloat16 h1 = __float2bfloat16(v.y);
    __nv_bfloat16 h2 = __float2bfloat16(v.z);
    __nv_bfloat16 h3 = __float2bfloat16(v.w);
    __nv_bfloat16 l0 = __float2bfloat16(v.x - __bfloat162float(h0));
    __nv_bfloat16 l1 = __float2bfloat16(v.y - __bfloat162float(h1));
    __nv_bfloat16 l2 = __float2bfloat16(v.z - __bfloat162float(h2));
    __nv_bfloat16 l3 = __float2bfloat16(v.w - __bfloat162float(h3));
    __nv_bfloat162 hp0 = {h0, h1}, hp1 = {h2, h3};
    __nv_bfloat162 lp0 = {l0, l1}, lp1 = {l2, l3};
    uint2 hv = {*(uint32_t*)&hp0, *(uint32_t*)&hp1};
    uint2 lv = {*(uint32_t*)&lp0, *(uint32_t*)&lp1};
    *reinterpret_cast<uint2*>(hi + (size_t)i * 4) = hv;
    *reinterpret_cast<uint2*>(lo + (size_t)i * 4) = lv;
}

// W [K, N] fp32 -> Wt hi/lo [N, K] bf16
__global__ __launch_bounds__(256) void wsplit_kernel(
    const float* __restrict__ W, __nv_bfloat16* __restrict__ Thi,
    __nv_bfloat16* __restrict__ Tlo, int K, int N)
{
    __shared__ float t[32][33];
    const int n0 = blockIdx.x * 32, k0 = blockIdx.y * 32;
    const int tx = threadIdx.x, ty = threadIdx.y;   // block (32, 8)
    for (int i = ty; i < 32; i += 8)
        t[i][tx] = W[(size_t)(k0 + i) * N + n0 + tx];
    __syncthreads();
    for (int i = ty; i < 32; i += 8) {
        float v = t[tx][i];                          // = W[k0+tx][n0+i]
        __nv_bfloat16 h = __float2bfloat16(v);
        __nv_bfloat16 l = __float2bfloat16(v - __bfloat162float(h));
        Thi[(size_t)(n0 + i) * K + k0 + tx] = h;
        Tlo[(size_t)(n0 + i) * K + k0 + tx] = l;
    }
}

// ===================== mma.sync bf16x3 GEMM =================================
// C[M,512] = [A0 | A1] @ B^T + bias (opt tanh), fp32 out.
// A row stride 512 bf16; B is [N=512, Ktot] bf16 (pre-transposed W).
// Block tile 128x128, K chunks of 32. Warps: 2(m) x 4(n), warp tile 64x32.
// Three accumulation passes per chunk: Ah*Bh + Ah*Bl + Al*Bh (fp32 accum).

#define SMP 40   // padded smem row stride in bf16 (80B = 20 banks: conflict-free)

__device__ __forceinline__ void mma_bf16(float* c, const uint32_t* a,
                                         const uint32_t* b) {
    asm volatile(
        "mma.sync.aligned.m16n8k16.row.col.f32.bf16.bf16.f32 "
        "{%0,%1,%2,%3}, {%4,%5,%6,%7}, {%8,%9}, {%0,%1,%2,%3};\n"
        : "+f"(c[0]), "+f"(c[1]), "+f"(c[2]), "+f"(c[3])
        : "r"(a[0]), "r"(a[1]), "r"(a[2]), "r"(a[3]), "r"(b[0]), "r"(b[1]));
}

__global__ __launch_bounds__(256, 1) void gemm_tc_kernel(
    const __nv_bfloat16* __restrict__ A0h, const __nv_bfloat16* __restrict__ A0l,
    const __nv_bfloat16* __restrict__ A1h, const __nv_bfloat16* __restrict__ A1l,
    const __nv_bfloat16* __restrict__ Bh,  const __nv_bfloat16* __restrict__ Bl,
    const float* __restrict__ bias, float* __restrict__ C,
    int Ktot, int do_tanh)
{
    __shared__ __nv_bfloat16 sAh[128 * SMP];
    __shared__ __nv_bfloat16 sAl[128 * SMP];
    __shared__ __nv_bfloat16 sBh[128 * SMP];
    __shared__ __nv_bfloat16 sBl[128 * SMP];

    const int tid  = threadIdx.x;
    const int wid  = tid >> 5, lane = tid & 31;
    const int wm   = wid >> 2;            // 0..1 -> m offset *64
    const int wn   = wid & 3;             // 0..3 -> n offset *32
    const int row0 = blockIdx.y * 128;
    const int col0 = blockIdx.x * 128;
    const int nchunk = Ktot / 32;

    const int lr = lane >> 2;             // 0..7
    const int lc = (lane & 3) * 2;        // 0,2,4,6

    float acc[4][4][4];
#pragma unroll
    for (int i = 0; i < 4; i++)
#pragma unroll
        for (int j = 0; j < 4; j++)
#pragma unroll
            for (int e = 0; e < 4; e++) acc[i][j][e] = 0.f;

    for (int kc = 0; kc < nchunk; kc++) {
        // --- pick A source (concat fold) ---
        int kk = kc * 32;
        const __nv_bfloat16 *ah, *al;
        if (kk < 512) { ah = A0h; al = A0l; }
        else          { ah = A1h; al = A1l; kk -= 512; }
        const int kb = kc * 32;           // B spans full Ktot

        if (kc > 0) __syncthreads();      // protect smem reuse

        // --- load 4 tiles (128 rows x 32 bf16 each): 512 uint4 per tile ---
#pragma unroll
        for (int it = 0; it < 2; it++) {
            const int idx = tid + it * 256;       // 0..511
            const int r   = idx >> 2;             // 0..127
            const int cs  = (idx & 3) * 8;        // bf16 seg offset
            *reinterpret_cast<uint4*>(&sAh[r * SMP + cs]) =
                *reinterpret_cast<const uint4*>(ah + (size_t)(row0 + r) * 512 + kk + cs);
            *reinterpret_cast<uint4*>(&sAl[r * SMP + cs]) =
                *reinterpret_cast<const uint4*>(al + (size_t)(row0 + r) * 512 + kk + cs);
            *reinterpret_cast<uint4*>(&sBh[r * SMP + cs]) =
                *reinterpret_cast<const uint4*>(Bh + (size_t)(col0 + r) * Ktot + kb + cs);
            *reinterpret_cast<uint4*>(&sBl[r * SMP + cs]) =
                *reinterpret_cast<const uint4*>(Bl + (size_t)(col0 + r) * Ktot + kb + cs);
        }
        __syncthreads();

        // --- compute: 2 k-steps of 16 ---
#pragma unroll
        for (int k0 = 0; k0 < 32; k0 += 16) {
            // A fragments (hi & lo) for 4 m-frags
            uint32_t afh[4][4], afl[4][4];
#pragma unroll
            for (int i = 0; i < 4; i++) {
                const int r = wm * 64 + i * 16 + lr;
                afh[i][0] = *reinterpret_cast<const uint32_t*>(&sAh[(r    ) * SMP + k0 + lc    ]);
                afh[i][1] = *reinterpret_cast<const uint32_t*>(&sAh[(r + 8) * SMP + k0 + lc    ]);
                afh[i][2] = *reinterpret_cast<const uint32_t*>(&sAh[(r    ) * SMP + k0 + lc + 8]);
                afh[i][3] = *reinterpret_cast<const uint32_t*>(&sAh[(r + 8) * SMP + k0 + lc + 8]);
                afl[i][0] = *reinterpret_cast<const uint32_t*>(&sAl[(r    ) * SMP + k0 + lc    ]);
                afl[i][1] = *reinterpret_cast<const uint32_t*>(&sAl[(r + 8) * SMP + k0 + lc    ]);
                afl[i][2] = *reinterpret_cast<const uint32_t*>(&sAl[(r    ) * SMP + k0 + lc + 8]);
                afl[i][3] = *reinterpret_cast<const uint32_t*>(&sAl[(r + 8) * SMP + k0 + lc + 8]);
            }
#pragma unroll
            for (int j = 0; j < 4; j++) {
                const int n = wn * 32 + j * 8 + lr;
                uint32_t bh[2], bl[2];
                bh[0] = *reinterpret_cast<const uint32_t*>(&sBh[n * SMP + k0 + lc    ]);
                bh[1] = *reinterpret_cast<const uint32_t*>(&sBh[n * SMP + k0 + lc + 8]);
                bl[0] = *reinterpret_cast<const uint32_t*>(&sBl[n * SMP + k0 + lc    ]);
                bl[1] = *reinterpret_cast<const uint32_t*>(&sBl[n * SMP + k0 + lc + 8]);
#pragma unroll
                for (int i = 0; i < 4; i++) {
                    mma_bf16(acc[i][j], afh[i], bh);   // hi*hi
                    mma_bf16(acc[i][j], afh[i], bl);   // hi*lo
                    mma_bf16(acc[i][j], afl[i], bh);   // lo*hi
                }
            }
        }
    }

    // --- epilogue: bias (+tanh), direct global stores ---
#pragma unroll
    for (int i = 0; i < 4; i++) {
        const int r = row0 + wm * 64 + i * 16 + lr;
#pragma unroll
        for (int j = 0; j < 4; j++) {
            const int c = col0 + wn * 32 + j * 8 + lc;
            float2 v0, v1;
            v0.x = acc[i][j][0] + bias[c];
            v0.y = acc[i][j][1] + bias[c + 1];
            v1.x = acc[i][j][2] + bias[c];
            v1.y = acc[i][j][3] + bias[c + 1];
            if (do_tanh) {
                v0.x = tanhf(v0.x); v0.y = tanhf(v0.y);
                v1.x = tanhf(v1.x); v1.y = tanhf(v1.y);
            }
            *reinterpret_cast<float2*>(C + (size_t)r * 512 + c)       = v0;
            *reinterpret_cast<float2*>(C + (size_t)(r + 8) * 512 + c) = v1;
        }
    }
}

// ---------------- flash attention (unchanged, verified R3) ------------------
#define ATTN_SMEM_FLOATS (64*65*3 + 64*68 + 192)
#define ATTN_SMEM_BYTES  (ATTN_SMEM_FLOATS * 4)

__global__ __launch_bounds__(256) void attn_kernel()
{
    extern __shared__ float sm[];
    float* Qst  = sm;
    float* Kst  = Qst + 64 * 65;
    float* Vs   = Kst + 64 * 65;
    float* Ss   = Vs  + 64 * 68;
    float* mrow = Ss  + 64 * 65;
    float* lrow = mrow + 64;
    float* frow = lrow + 64;

    const int tid = threadIdx.x;
    const int tx = tid & 15, ty = tid >> 4;
    const int qt = blockIdx.x, h = blockIdx.y, b = blockIdx.z;
    const int qrow0 = b * SEQ + qt * 64;
    const int colh  = h * HDIM;

    for (int idx = tid; idx < 64 * 16; idx += 256) {
        int r = idx >> 4, dv = (idx & 15) * 4;
        float4 v = *reinterpret_cast<const float4*>(
            g_q + (size_t)(qrow0 + r) * F + colh + dv);
        Qst[(dv + 0) * 65 + r] = v.x; Qst[(dv + 1) * 65 + r] = v.y;
        Qst[(dv + 2) * 65 + r] = v.z; Qst[(dv + 3) * 65 + r] = v.w;
    }
    if (tid < 64) { mrow[tid] = -CUDART_INF_F; lrow[tid] = 0.f; }

    const int i0 = ty * 4, n0 = tx * 4;
    float acc[4][4] = {};

    for (int kt = 0; kt < SEQ / 64; kt++) {
        const int krow0 = b * SEQ + kt * 64;
        __syncthreads();
        for (int idx = tid; idx < 64 * 16; idx += 256) {
            int r = idx >> 4, dv = (idx & 15) * 4;
            float4 kv = *reinterpret_cast<const float4*>(
                g_k + (size_t)(krow0 + r) * F + colh + dv);
            Kst[(dv + 0) * 65 + r] = kv.x; Kst[(dv + 1) * 65 + r] = kv.y;
            Kst[(dv + 2) * 65 + r] = kv.z; Kst[(dv + 3) * 65 + r] = kv.w;
            float4 vv = *reinterpret_cast<const float4*>(
                g_v + (size_t)(krow0 + r) * F + colh + dv);
            *reinterpret_cast<float4*>(&Vs[r * 68 + dv]) = vv;
        }
        __syncthreads();

        float s[4][4] = {};
#pragma unroll
        for (int d = 0; d < 64; d++) {
            float a[4], bb[4];
#pragma unroll
            for (int i = 0; i < 4; i++) a[i]  = Qst[d * 65 + i0 + i];
#pragma unroll
            for (int j = 0; j < 4; j++) bb[j] = Kst[d * 65 + n0 + j];
#pragma unroll
            for (int i = 0; i < 4; i++)
#pragma unroll
                for (int j = 0; j < 4; j++)
                    s[i][j] = fmaf(a[i], bb[j], s[i][j]);
        }
#pragma unroll
        for (int i = 0; i < 4; i++)
#pragma unroll
            for (int j = 0; j < 4; j++)
                Ss[(i0 + i) * 65 + n0 + j] = s[i][j] * 0.125f;
        __syncthreads();

        {
            const int warp = tid >> 5, lane = tid & 31;
            for (int rr = 0; rr < 8; rr++) {
                const int r = warp * 8 + rr;
                float v0 = Ss[r * 65 + lane];
                float v1 = Ss[r * 65 + lane + 32];
                float mx = fmaxf(v0, v1);
#pragma unroll
                for (int off = 16; off; off >>= 1)
                    mx = fmaxf(mx, __shfl_xor_sync(0xffffffffu, mx, off));
                const float mold = mrow[r];
                const float mnew = fmaxf(mold, mx);
                const float p0 = __expf(v0 - mnew);
                const float p1 = __expf(v1 - mnew);
                float ssum = p0 + p1;
#pragma unroll
                for (int off = 16; off; off >>= 1)
                    ssum += __shfl_xor_sync(0xffffffffu, ssum, off);
                Ss[r * 65 + lane]      = p0;
                Ss[r * 65 + lane + 32] = p1;
                if (lane == 0) {
                    const float fr = __expf(mold - mnew);
                    frow[r] = fr;
                    lrow[r] = lrow[r] * fr + ssum;
                    mrow[r] = mnew;
                }
            }
        }
        __syncthreads();

        float f[4];
#pragma unroll
        for (int i = 0; i < 4; i++) f[i] = frow[i0 + i];
#pragma unroll
        for (int i = 0; i < 4; i++)
#pragma unroll
            for (int n = 0; n < 4; n++) acc[i][n] *= f[i];
#pragma unroll
        for (int j = 0; j < 64; j++) {
            float a[4], bb[4];
#pragma unroll
            for (int i = 0; i < 4; i++) a[i]  = Ss[(i0 + i) * 65 + j];
#pragma unroll
            for (int n = 0; n < 4; n++) bb[n] = Vs[j * 68 + n0 + n];
#pragma unroll
            for (int i = 0; i < 4; i++)
#pragma unroll
                for (int n = 0; n < 4; n++)
                    acc[i][n] = fmaf(a[i], bb[n], acc[i][n]);
        }
    }
    __syncthreads();

#pragma unroll
    for (int i = 0; i < 4; i++) {
        const float linv = 1.f / lrow[i0 + i];
        const int row = qrow0 + i0 + i;
        float4 v;
        v.x = acc[i][0] * linv; v.y = acc[i][1] * linv;
        v.z = acc[i][2] * linv; v.w = acc[i][3] * linv;
        *reinterpret_cast<float4*>(g_ctx + (size_t)row * F + colh + n0) = v;
    }
}

// ---------------- launch ----------------------------------------------------
extern "C" void kernel_launch(void* const* d_in, const int* in_sizes, int n_in,
                              void* d_out, int out_size)
{
    const float* Q  = (const float*)d_in[0];
    const float* K  = (const float*)d_in[1];
    const float* V  = (const float*)d_in[2];
    const float* Wq = (const float*)d_in[3];
    const float* bq = (const float*)d_in[4];
    const float* Wk = (const float*)d_in[5];
    const float* bk = (const float*)d_in[6];
    const float* Wv = (const float*)d_in[7];
    const float* bv = (const float*)d_in[8];
    const float* Wo = (const float*)d_in[9];
    const float* bo = (const float*)d_in[10];
    float* out = (float*)d_out;

    float *pq, *pk, *pv, *pc;
    cudaGetSymbolAddress((void**)&pq, g_q);
    cudaGetSymbolAddress((void**)&pk, g_k);
    cudaGetSymbolAddress((void**)&pv, g_v);
    cudaGetSymbolAddress((void**)&pc, g_ctx);
    __nv_bfloat16 *qih, *qil, *kih, *kil, *vih, *vil, *cxh, *cxl;
    __nv_bfloat16 *wqh, *wql, *wkh, *wkl, *wvh, *wvl, *woh, *wol;
    cudaGetSymbolAddress((void**)&qih, g_qin_hi); cudaGetSymbolAddress((void**)&qil, g_qin_lo);
    cudaGetSymbolAddress((void**)&kih, g_kin_hi); cudaGetSymbolAddress((void**)&kil, g_kin_lo);
    cudaGetSymbolAddress((void**)&vih, g_vin_hi); cudaGetSymbolAddress((void**)&vil, g_vin_lo);
    cudaGetSymbolAddress((void**)&cxh, g_ctx_hi); cudaGetSymbolAddress((void**)&cxl, g_ctx_lo);
    cudaGetSymbolAddress((void**)&wqh, g_wqt_hi); cudaGetSymbolAddress((void**)&wql, g_wqt_lo);
    cudaGetSymbolAddress((void**)&wkh, g_wkt_hi); cudaGetSymbolAddress((void**)&wkl, g_wkt_lo);
    cudaGetSymbolAddress((void**)&wvh, g_wvt_hi); cudaGetSymbolAddress((void**)&wvl, g_wvt_lo);
    cudaGetSymbolAddress((void**)&woh, g_wot_hi); cudaGetSymbolAddress((void**)&wol, g_wot_lo);

    cudaFuncSetAttribute(attn_kernel,
                         cudaFuncAttributeMaxDynamicSharedMemorySize, ATTN_SMEM_BYTES);

    const int n4 = MROWS * F / 4;           // 2097152 float4
    const int nb = (n4 + 255) / 256;

    // split inputs into bf16 hi/lo
    split_kernel<<<nb, 256>>>((const float4*)Q, qih, qil, n4);
    split_kernel<<<nb, 256>>>((const float4*)K, kih, kil, n4);
    split_kernel<<<nb, 256>>>((const float4*)V, vih, vil, n4);
    // transpose+split weights -> [N, K]
    wsplit_kernel<<<dim3(F/32, F/32),   dim3(32, 8)>>>(Wq, wqh, wql, F, F);
    wsplit_kernel<<<dim3(F/32, F/32),   dim3(32, 8)>>>(Wk, wkh, wkl, F, F);
    wsplit_kernel<<<dim3(F/32, F/32),   dim3(32, 8)>>>(Wv, wvh, wvl, F, F);
    wsplit_kernel<<<dim3(F/32, 2*F/32), dim3(32, 8)>>>(Wo, woh, wol, 2*F, F);

    const dim3 ggemm(F / 128, MROWS / 128);   // (4, 128)
    // QKV projections on tensor cores (mma.sync bf16x3)
    gemm_tc_kernel<<<ggemm, 256>>>(qih, qil, qih, qil, wqh, wql, bq, pq, F, 0);
    gemm_tc_kernel<<<ggemm, 256>>>(kih, kil, kih, kil, wkh, wkl, bk, pk, F, 0);
    gemm_tc_kernel<<<ggemm, 256>>>(vih, vil, vih, vil, wvh, wvl, bv, pv, F, 0);

    // attention (fp32 SIMT, verified)
    attn_kernel<<<dim3(SEQ / 64, NHEAD, 16), 256, ATTN_SMEM_BYTES>>>();

    // split ctx, then output GEMM: tanh([ctx | Q] @ Wo + bo)
    split_kernel<<<nb, 256>>>((const float4*)pc, cxh, cxl, n4);
    gemm_tc_kernel<<<ggemm, 256>>>(cxh, cxl, qih, qil, woh, wol, bo, out, 2 * F, 1);
}